// round 5
// baseline (speedup 1.0000x reference)
#include <cuda_runtime.h>
#include <cuda_bf16.h>
#include <stdint.h>

// ---------------- problem constants ----------------
#define D_IN    1024
#define D_OUT   1024
#define RANK    16
#define SCALING 2.0f          // alpha / rank = 32/16
#define M_MAX   32768         // B*S = 4*8192

// ---------------- GEMM tiling ----------------
#define TM      128
#define TN      128
#define KC      64            // k-chunk per stage
#define NCHUNK  (D_IN / KC)   // 16
#define STAGES  3
#define NTHR    256

#define TILE_B  (TM * KC * 2)         // 16384 bytes (128 rows x 64 bf16)
#define S_AHI   0
#define S_ALO   (1 * TILE_B)
#define S_BHI   (2 * TILE_B)
#define S_BLO   (3 * TILE_B)
#define STAGE_B (4 * TILE_B)          // 65536
#define SMEM_TOT (STAGES * STAGE_B)   // 196608

// ---------------- device scratch (static: no allocs allowed) ----------------
__device__ __align__(128) __nv_bfloat16 g_whi[D_OUT * D_IN];
__device__ __align__(128) __nv_bfloat16 g_wlo[D_OUT * D_IN];
__device__ __align__(128) __nv_bfloat16 g_xhi[(size_t)M_MAX * D_IN];
__device__ __align__(128) __nv_bfloat16 g_xlo[(size_t)M_MAX * D_IN];

// ---------------- helpers ----------------
__device__ __forceinline__ uint32_t smem_u32(const void* p) {
    uint32_t a;
    asm("{ .reg .u64 t; cvta.to.shared.u64 t, %1; cvt.u32.u64 %0, t; }"
        : "=r"(a) : "l"(p));
    return a;
}

__device__ __forceinline__ void cp16(uint32_t saddr, const void* gptr) {
    asm volatile("cp.async.cg.shared.global [%0], [%1], 16;"
                 :: "r"(saddr), "l"(gptr) : "memory");
}
#define CP_COMMIT()  asm volatile("cp.async.commit_group;" ::: "memory")
#define CP_WAIT(n)   asm volatile("cp.async.wait_group %0;" :: "n"(n) : "memory")

#define LDSM4(R, addr)                                                        \
    asm volatile("ldmatrix.sync.aligned.m8n8.x4.shared.b16 {%0,%1,%2,%3}, [%4];" \
                 : "=r"((R)[0]), "=r"((R)[1]), "=r"((R)[2]), "=r"((R)[3])     \
                 : "r"(addr))

#define MMA_BF16(d, a, b0, b1)                                                \
    asm volatile("mma.sync.aligned.m16n8k16.row.col.f32.bf16.bf16.f32 "       \
                 "{%0,%1,%2,%3}, {%4,%5,%6,%7}, {%8,%9}, {%0,%1,%2,%3};"      \
                 : "+f"((d)[0]), "+f"((d)[1]), "+f"((d)[2]), "+f"((d)[3])     \
                 : "r"((a)[0]), "r"((a)[1]), "r"((a)[2]), "r"((a)[3]),        \
                   "r"(b0), "r"(b1))

__device__ __forceinline__ uint32_t pack_hi(float a, float b, uint32_t& lo) {
    __nv_bfloat16 ha = __float2bfloat16_rn(a);
    __nv_bfloat16 hb = __float2bfloat16_rn(b);
    __nv_bfloat16 la = __float2bfloat16_rn(a - __bfloat162float(ha));
    __nv_bfloat16 lb = __float2bfloat16_rn(b - __bfloat162float(hb));
    lo = (uint32_t)__bfloat16_as_ushort(la) | ((uint32_t)__bfloat16_as_ushort(lb) << 16);
    return (uint32_t)__bfloat16_as_ushort(ha) | ((uint32_t)__bfloat16_as_ushort(hb) << 16);
}

// ---------------- prep 1: effective weight, scale-folded, hi/lo split ----------------
__global__ void __launch_bounds__(256) dora_prep_kernel(
    const float* __restrict__ W, const float* __restrict__ a_w,
    const float* __restrict__ b_w, const float* __restrict__ mag) {
    const int o = blockIdx.x;
    const int t = threadIdx.x;

    __shared__ float b_sh[RANK];
    __shared__ float red[256];
    __shared__ float scale_sh;

    if (t < RANK) b_sh[t] = b_w[o * RANK + t];
    __syncthreads();

    float vals[4];
    float ss = 0.0f;
#pragma unroll
    for (int i = 0; i < 4; i++) {
        int d = t + i * 256;
        float acc = W[(size_t)o * D_IN + d];
        float l = 0.0f;
#pragma unroll
        for (int r = 0; r < RANK; r++)
            l += b_sh[r] * a_w[r * D_IN + d];
        acc += SCALING * l;
        vals[i] = acc;
        ss += acc * acc;
    }

    red[t] = ss;
    __syncthreads();
#pragma unroll
    for (int s = 128; s > 0; s >>= 1) {
        if (t < s) red[t] += red[t + s];
        __syncthreads();
    }
    if (t == 0) scale_sh = mag[o] / sqrtf(red[0]);
    __syncthreads();
    const float scale = scale_sh;

#pragma unroll
    for (int i = 0; i < 4; i++) {
        int d = t + i * 256;
        float sv = vals[i] * scale;
        __nv_bfloat16 h = __float2bfloat16_rn(sv);
        __nv_bfloat16 l = __float2bfloat16_rn(sv - __bfloat162float(h));
        g_whi[(size_t)o * D_IN + d] = h;
        g_wlo[(size_t)o * D_IN + d] = l;
    }
}

// ---------------- prep 2: x fp32 -> bf16 hi/lo global split ----------------
__global__ void __launch_bounds__(256) xsplit_kernel(const float* __restrict__ x, int total8) {
    int i = blockIdx.x * 256 + threadIdx.x;
    if (i >= total8) return;
    size_t base = (size_t)i * 8;
    float4 v0 = *reinterpret_cast<const float4*>(x + base);
    float4 v1 = *reinterpret_cast<const float4*>(x + base + 4);
    float f[8] = {v0.x, v0.y, v0.z, v0.w, v1.x, v1.y, v1.z, v1.w};
    uint32_t hw[4], lw[4];
#pragma unroll
    for (int j = 0; j < 4; j++)
        hw[j] = pack_hi(f[2 * j], f[2 * j + 1], lw[j]);
    *reinterpret_cast<uint4*>(g_xhi + base) = make_uint4(hw[0], hw[1], hw[2], hw[3]);
    *reinterpret_cast<uint4*>(g_xlo + base) = make_uint4(lw[0], lw[1], lw[2], lw[3]);
}

// ---------------- GEMM: out[M,1024] = x @ w_s^T (3-pass bf16-split HMMA) ----------------
__global__ void __launch_bounds__(NTHR, 1) dora_gemm_kernel(float* __restrict__ out) {
    extern __shared__ char smem_raw[];
    const uint32_t sb = smem_u32(smem_raw);

    const int tid  = threadIdx.x;
    const int lane = tid & 31;
    const int warp = tid >> 5;
    const int n0 = blockIdx.x * TN;
    const int m0 = blockIdx.y * TM;

    // ---- per-thread cp.async offsets (4 iters x 4 buffers) ----
    // tile: 128 rows x 64 bf16 (128B rows). swizzle: byte ^ ((row&7)<<4).
    uint32_t soff[4];
    uint32_t goffA[4], goffB[4];   // element offsets (relative to m0/n0 row base)
#pragma unroll
    for (int i = 0; i < 4; i++) {
        int idx = tid + i * NTHR;          // 0..1023
        int row = idx >> 3;
        int c8  = idx & 7;                 // 16B chunk within row
        soff[i]  = (uint32_t)(row * 128 + ((c8 * 16) ^ ((row & 7) << 4)));
        goffA[i] = (uint32_t)(row * D_IN + c8 * 8);
        goffB[i] = (uint32_t)(row * D_IN + c8 * 8);
    }
    const __nv_bfloat16* xhiB = g_xhi + (size_t)m0 * D_IN;
    const __nv_bfloat16* xloB = g_xlo + (size_t)m0 * D_IN;
    const __nv_bfloat16* whiB = g_whi + (size_t)n0 * D_IN;
    const __nv_bfloat16* wloB = g_wlo + (size_t)n0 * D_IN;

#define LOAD_STAGE(kc_, slot_)                                               \
    do {                                                                     \
        uint32_t k0_ = (uint32_t)(kc_) * KC;                                 \
        uint32_t b_ = sb + (uint32_t)(slot_) * STAGE_B;                      \
        _Pragma("unroll")                                                    \
        for (int i_ = 0; i_ < 4; i_++) {                                     \
            cp16(b_ + S_AHI + soff[i_], xhiB + goffA[i_] + k0_);             \
            cp16(b_ + S_ALO + soff[i_], xloB + goffA[i_] + k0_);             \
            cp16(b_ + S_BHI + soff[i_], whiB + goffB[i_] + k0_);             \
            cp16(b_ + S_BLO + soff[i_], wloB + goffB[i_] + k0_);             \
        }                                                                    \
    } while (0)

    // ---- warp tiling: 2 (M) x 4 (N); warp tile 64x32 ----
    const int wm = warp & 1;
    const int wn = warp >> 1;
    const int q = lane >> 3;
    const int r = lane & 7;

    // ldmatrix lane addressing (A: m16k16 tiles; B: n16k16 blocks)
    uint32_t a_base[4], a_xor[4];
#pragma unroll
    for (int mt = 0; mt < 4; mt++) {
        int arow = wm * 64 + mt * 16 + (q & 1) * 8 + r;
        a_base[mt] = (uint32_t)(arow * 128);
        a_xor[mt]  = (uint32_t)((arow & 7) << 4);
    }
    const uint32_t a_kb = (uint32_t)((q >> 1) * 16);   // bytes within row
    uint32_t b_base[2], b_xor[2];
#pragma unroll
    for (int bt = 0; bt < 2; bt++) {
        int brow = wn * 32 + bt * 16 + (q >> 1) * 8 + r;
        b_base[bt] = (uint32_t)(brow * 128);
        b_xor[bt]  = (uint32_t)((brow & 7) << 4);
    }
    const uint32_t b_kb = (uint32_t)((q & 1) * 16);

    float acc[4][4][4];
#pragma unroll
    for (int mt = 0; mt < 4; mt++)
#pragma unroll
        for (int nt = 0; nt < 4; nt++)
#pragma unroll
            for (int j = 0; j < 4; j++) acc[mt][nt][j] = 0.0f;

    // ---- pipeline prologue: prefetch 2 stages ----
    LOAD_STAGE(0, 0); CP_COMMIT();
    LOAD_STAGE(1, 1); CP_COMMIT();

    for (int kc = 0; kc < NCHUNK; kc++) {
        CP_WAIT(1);          // stage kc landed (<=1 group pending)
        __syncthreads();     // visible to all warps; prev compute done

        if (kc + 2 < NCHUNK) LOAD_STAGE(kc + 2, (kc + 2) % STAGES);
        CP_COMMIT();         // commit every iter (empty ok) to keep count uniform

        const uint32_t sA = sb + (uint32_t)(kc % STAGES) * STAGE_B;
#pragma unroll
        for (int ks = 0; ks < 4; ks++) {
            const uint32_t akb = a_kb + (uint32_t)ks * 32;
            const uint32_t bkb = b_kb + (uint32_t)ks * 32;

            uint32_t AH[4][4], AL[4][4];
#pragma unroll
            for (int mt = 0; mt < 4; mt++) {
                uint32_t off = a_base[mt] + (akb ^ a_xor[mt]);
                LDSM4(AH[mt], sA + S_AHI + off);
                LDSM4(AL[mt], sA + S_ALO + off);
            }
            uint32_t BH[2][4], BL[2][4];
#pragma unroll
            for (int bt = 0; bt < 2; bt++) {
                uint32_t off = b_base[bt] + (bkb ^ b_xor[bt]);
                LDSM4(BH[bt], sA + S_BHI + off);
                LDSM4(BL[bt], sA + S_BLO + off);
            }
#pragma unroll
            for (int mt = 0; mt < 4; mt++) {
#pragma unroll
                for (int nt = 0; nt < 4; nt++) {
                    const int bt = nt >> 1, s = (nt & 1) * 2;
                    MMA_BF16(acc[mt][nt], AH[mt], BH[bt][s], BH[bt][s + 1]);
                    MMA_BF16(acc[mt][nt], AH[mt], BL[bt][s], BL[bt][s + 1]);
                    MMA_BF16(acc[mt][nt], AL[mt], BH[bt][s], BH[bt][s + 1]);
                }
            }
        }
    }

    // ---- epilogue: direct global stores ----
    const int gm = lane >> 2;           // group id
    const int gn = (lane & 3) * 2;
#pragma unroll
    for (int mt = 0; mt < 4; mt++) {
#pragma unroll
        for (int nt = 0; nt < 4; nt++) {
            const int m = m0 + wm * 64 + mt * 16 + gm;
            const int n = n0 + wn * 32 + nt * 8 + gn;
            float2* p0 = reinterpret_cast<float2*>(out + (size_t)m * D_OUT + n);
            float2* p1 = reinterpret_cast<float2*>(out + (size_t)(m + 8) * D_OUT + n);
            *p0 = make_float2(acc[mt][nt][0], acc[mt][nt][1]);
            *p1 = make_float2(acc[mt][nt][2], acc[mt][nt][3]);
        }
    }
}

// ---------------- launch ----------------
extern "C" void kernel_launch(void* const* d_in, const int* in_sizes, int n_in,
                              void* d_out, int out_size) {
    const float* x   = (const float*)d_in[0];   // [B,S,D_IN]
    const float* W   = (const float*)d_in[1];   // [D_OUT, D_IN]
    const float* a_w = (const float*)d_in[2];   // [R, D_IN]
    const float* b_w = (const float*)d_in[3];   // [D_OUT, R]
    const float* mag = (const float*)d_in[4];   // [1, D_OUT]
    float* out = (float*)d_out;

    const int M = in_sizes[0] / D_IN;           // 32768

    dora_prep_kernel<<<D_OUT, 256>>>(W, a_w, b_w, mag);

    const int total8 = M * D_IN / 8;
    xsplit_kernel<<<(total8 + 255) / 256, 256>>>(x, total8);

    cudaFuncSetAttribute(dora_gemm_kernel,
                         cudaFuncAttributeMaxDynamicSharedMemorySize, SMEM_TOT);
    dim3 grid(D_OUT / TN, M / TM);              // (8, 256) — n fastest: x L2 reuse
    dora_gemm_kernel<<<grid, NTHR, SMEM_TOT>>>(out);
}